// round 14
// baseline (speedup 1.0000x reference)
#include <cuda_runtime.h>
#include <cuda_bf16.h>
#include <cuda_fp16.h>
#include <cooperative_groups.h>

namespace cg = cooperative_groups;

#define BN_ 32
#define TN_ 1024
#define DN_ 1024
#define ON_ 256
#define CS_ 4
#define SC_ (TN_/CS_)   /* 256 s-rows per CTA */
#define NT_ 512         /* threads in recur kernel */
#define NW_ 16          /* warps */
#define RPW_ (SC_/NW_)  /* 16 rows per warp */

// ---- device scratch (static: no runtime allocation) ----
__device__ __align__(128) __half         g_UaH[(size_t)BN_*TN_*ON_]; // inputs@Ua + Ba2  (fp16)
__device__ __align__(128) __nv_bfloat16  g_IC [(size_t)BN_*TN_*ON_]; // inputs@Co        (bf16)
__device__ __align__(128) float          g_UoH[(size_t)BN_*TN_*ON_]; // inputs@Uo + Bo2  (fp32)
__device__ float g_w2[ON_];                                           // emb @ Wo

__device__ __forceinline__ float tanh_a(float x){
    float y; asm("tanh.approx.f32 %0, %1;" : "=f"(y) : "f"(x)); return y;
}
__device__ __forceinline__ __half2 tanh2_a(__half2 x){
    unsigned xi = *reinterpret_cast<unsigned*>(&x), r;
    asm("tanh.approx.f16x2 %0, %1;" : "=r"(r) : "r"(xi));
    return *reinterpret_cast<__half2*>(&r);
}
__device__ __forceinline__ void bf8(const uint4 u, float f[8]){
    f[0]=__int_as_float(u.x<<16); f[1]=__int_as_float(u.x&0xffff0000u);
    f[2]=__int_as_float(u.y<<16); f[3]=__int_as_float(u.y&0xffff0000u);
    f[4]=__int_as_float(u.z<<16); f[5]=__int_as_float(u.z&0xffff0000u);
    f[6]=__int_as_float(u.w<<16); f[7]=__int_as_float(u.w&0xffff0000u);
}

// ---- cluster mbarrier barrier + remote STS (push model) ----
__device__ __forceinline__ void bar_arrive_rank(unsigned addr, unsigned rank){
    asm volatile("{\n\t.reg .b32 ra;\n\t"
                 "mapa.shared::cluster.u32 ra, %0, %1;\n\t"
                 "mbarrier.arrive.release.cluster.shared::cluster.b64 _, [ra];\n\t}"
                 :: "r"(addr), "r"(rank) : "memory");
}
__device__ __forceinline__ void bar_wait(unsigned addr, unsigned parity){
    unsigned done;
    do {
        asm volatile("{\n\t.reg .pred p;\n\t"
            "mbarrier.try_wait.parity.acquire.cluster.shared::cta.b64 p, [%1], %2, 0x989680;\n\t"
            "selp.b32 %0, 1, 0, p;\n\t}"
            : "=r"(done) : "r"(addr), "r"(parity) : "memory");
    } while (!done);
}
__device__ __forceinline__ void sts_remote(unsigned addr, unsigned rank, float v){
    asm volatile("{\n\t.reg .b32 ra;\n\t"
                 "mapa.shared::cluster.u32 ra, %0, %1;\n\t"
                 "st.shared::cluster.f32 [ra], %2;\n\t}"
                 :: "r"(addr), "r"(rank), "f"(v) : "memory");
}

// ================= w2 = emb @ Wo =================
__global__ void __launch_bounds__(256) w2_kernel(const float* __restrict__ emb,
                                                 const float* __restrict__ Wo){
    int w = threadIdx.x >> 5, lane = threadIdx.x & 31;
    int i = blockIdx.x * 8 + w;
    float a = 0.f;
    #pragma unroll
    for (int j = lane; j < ON_; j += 32) a = fmaf(emb[i*ON_+j], Wo[j], a);
    #pragma unroll
    for (int off=16; off; off>>=1) a += __shfl_xor_sync(0xffffffffu, a, off);
    if (lane==0) g_w2[i] = a;
}

// ======= fused precompute: [32768,1024] @ 3x[1024,256] =======
__global__ void __launch_bounds__(256,2) gemm_pre(
    const float* __restrict__ A,  const float* __restrict__ Ua,
    const float* __restrict__ Co, const float* __restrict__ Uo,
    const float* __restrict__ Ba2,const float* __restrict__ Bo2)
{
    __shared__ float As[16][128];
    __shared__ float Bs[16][128];
    const int tid = threadIdx.x;
    const int mt = blockIdx.x, nt = blockIdx.y;
    const int which = nt >> 1;
    const int ncol0 = (nt & 1) * 128;
    const float* Bmat = (which==0) ? Ua : ((which==1) ? Co : Uo);
    const int m0 = mt * 128;
    const int tx = tid & 15, ty = tid >> 4;

    float acc[8][8];
    #pragma unroll
    for (int i=0;i<8;i++)
        #pragma unroll
        for (int j=0;j<8;j++) acc[i][j]=0.f;

    for (int k0=0;k0<DN_;k0+=16){
        #pragma unroll
        for (int q=0;q<2;q++){
            int f4 = tid + q*256;
            int row = f4 >> 2, c4 = f4 & 3;
            float4 v = *(const float4*)&A[(size_t)(m0+row)*DN_ + k0 + c4*4];
            As[c4*4+0][row]=v.x; As[c4*4+1][row]=v.y;
            As[c4*4+2][row]=v.z; As[c4*4+3][row]=v.w;
        }
        #pragma unroll
        for (int q=0;q<2;q++){
            int f4 = tid + q*256;
            int kk = f4 >> 5, c4 = f4 & 31;
            *(float4*)&Bs[kk][c4*4] = *(const float4*)&Bmat[(size_t)(k0+kk)*ON_ + ncol0 + c4*4];
        }
        __syncthreads();
        #pragma unroll
        for (int kk=0;kk<16;kk++){
            float a[8], bb[8];
            *(float4*)&a[0]  = *(const float4*)&As[kk][ty*8];
            *(float4*)&a[4]  = *(const float4*)&As[kk][ty*8+4];
            *(float4*)&bb[0] = *(const float4*)&Bs[kk][tx*8];
            *(float4*)&bb[4] = *(const float4*)&Bs[kk][tx*8+4];
            #pragma unroll
            for (int i=0;i<8;i++)
                #pragma unroll
                for (int j=0;j<8;j++) acc[i][j] = fmaf(a[i], bb[j], acc[i][j]);
        }
        __syncthreads();
    }
    #pragma unroll
    for (int i=0;i<8;i++){
        int mrow = m0 + ty*8 + i;
        int trow = mrow & (TN_-1);
        #pragma unroll
        for (int j=0;j<8;j++){
            int c = ncol0 + tx*8 + j;
            float v = acc[i][j];
            size_t oi = (size_t)mrow*ON_ + c;
            if (which==0)      g_UaH[oi] = __float2half(v + Ba2[trow*ON_ + c]);
            else if (which==1) g_IC[oi]  = __float2bfloat16(v);
            else               g_UoH[oi] = v + Bo2[c];
        }
    }
}

#define WCI(j) ((((j)>>5)*33) + ((j)&31))
#define UAH_BYTES (SC_*ON_*2)          /* 131072: UaH chunk, smem-resident */

// ============ persistent per-batch cluster recurrence ============
__global__ void __cluster_dims__(CS_,1,1) __launch_bounds__(NT_,1)
recur_kernel(const float* __restrict__ Wa,  const float* __restrict__ Va,
             const float* __restrict__ Ba1, const float* __restrict__ Ba3,
             const float* __restrict__ Bo3, const float* __restrict__ Bo4,
             float* __restrict__ out)
{
    extern __shared__ __align__(128) char dsm[];
    char* s_uahB = dsm;                       // [256][256] fp16, row = 512B

    __shared__ float s_pred[ON_];
    __shared__ float s_q[ON_];
    __shared__ float s_was[ON_];              // full WaS (pushed by all ranks)
    __shared__ float s_ba3[SC_];
    __shared__ float s_b34[ON_];
    __shared__ float s_w2[ON_];
    __shared__ float s_wc[NW_][8*33];         // per-warp coc partials (swizzled)
    __shared__ float s_wl[NW_];
    __shared__ float s_cin[CS_][ON_+1];       // pushed partials: c[256], l
    __shared__ float s_redA[8], s_redB[8];
    __shared__ __align__(16) unsigned long long s_bars[2];

    cg::cluster_group cluster = cg::this_cluster();
    const int rank = blockIdx.x;
    const int b    = blockIdx.y;
    const int tid  = threadIdx.x;
    const int w = tid >> 5, lane = tid & 31;
    const unsigned FULL = 0xffffffffu;

    // ---- one-time init ----
    if (tid < ON_){
        s_pred[tid] = 0.f;
        s_b34[tid]  = Bo3[tid] + Bo4[tid];
        s_w2[tid]   = g_w2[tid];
    }
    if (tid < SC_) s_ba3[tid] = Ba3[rank*SC_ + tid];

    // Wa slice in registers: Wr[jj][k] = Wa[(lane+32k)][rank*64 + w*4 + jj]
    float Wr[4][8];
    #pragma unroll
    for (int jj=0;jj<4;jj++)
        #pragma unroll
        for (int k=0;k<8;k++)
            Wr[jj][k] = Wa[(size_t)(lane + 32*k)*ON_ + rank*64 + w*4 + jj];
    float ba1r[4];
    #pragma unroll
    for (int jj=0;jj<4;jj++) ba1r[jj] = Ba1[rank*64 + w*4 + jj];

    __half2 va_h2[4];
    #pragma unroll
    for (int j=0;j<4;j++)
        va_h2[j] = __floats2half2_rn(Va[lane*8+2*j], Va[lane*8+2*j+1]);

    unsigned barA = (unsigned)__cvta_generic_to_shared(&s_bars[0]);
    unsigned barB = (unsigned)__cvta_generic_to_shared(&s_bars[1]);
    unsigned wasA = (unsigned)__cvta_generic_to_shared(&s_was[0]);
    unsigned cinA = (unsigned)__cvta_generic_to_shared(&s_cin[0][0]);
    if (tid == 0){
        asm volatile("mbarrier.init.shared.b64 [%0], %1;" :: "r"(barA), "r"(CS_) : "memory");
        asm volatile("mbarrier.init.shared.b64 [%0], %1;" :: "r"(barB), "r"(CS_) : "memory");
    }

    const __half*        uahB = g_UaH + (size_t)b*TN_*ON_ + (size_t)rank*SC_*ON_;
    const __nv_bfloat16* icB  = g_IC  + (size_t)b*TN_*ON_ + (size_t)rank*SC_*ON_;
    const float* uohB = g_UoH + (size_t)b*TN_*ON_;
    float* outB = out + (size_t)b*TN_*ON_;

    // ---- load UaH chunk into smem once ----
    {
        const uint4* src = (const uint4*)uahB;
        uint4* dst = (uint4*)s_uahB;
        #pragma unroll
        for (int i=0;i<16;i++) dst[tid + i*NT_] = src[tid + i*NT_];
    }

    // per-warp IC global pointer (row stride = 32 uint4)
    const uint4* i4 = (const uint4*)icB + (size_t)(w*RPW_)*32 + lane;

    cluster.sync();   // once: mbarrier init visible cluster-wide

    for (int t=0; t<TN_; t++){
        const unsigned ph = (unsigned)(t & 1);

        float uoh = 0.f, woy = 0.f;
        if (tid < ON_)
            uoh = __ldcg(&uohB[(size_t)((t + TN_ - 1) & (TN_-1))*ON_ + tid]);

        // ---- phase 1: q = tanh(pred); woy = softmax(pred)·w2 (first 8 warps) ----
        if (tid < ON_){
            float pv = s_pred[tid];
            s_q[tid] = tanh_a(pv);
            float e  = __expf(pv);
            float en = e, ew = e * s_w2[tid];
            #pragma unroll
            for (int off=16; off; off>>=1){
                en += __shfl_xor_sync(FULL, en, off);
                ew += __shfl_xor_sync(FULL, ew, off);
            }
            if (lane==0){ s_redA[w]=en; s_redB[w]=ew; }
        }
        __syncthreads();
        if (tid < ON_){
            float sn=0.f, sw=0.f;
            #pragma unroll
            for (int r=0;r<8;r++){ sn+=s_redA[r]; sw+=s_redB[r]; }
            woy = sw / sn;
        }

        // ---- phase 2: this rank's WaS quarter, pushed to all ranks ----
        {
            float qr[8];
            #pragma unroll
            for (int k=0;k<8;k++) qr[k] = s_q[lane + 32*k];
            #pragma unroll
            for (int jj=0;jj<4;jj++){
                float p = 0.f;
                #pragma unroll
                for (int k=0;k<8;k++) p = fmaf(qr[k], Wr[jj][k], p);
                #pragma unroll
                for (int off=16; off; off>>=1) p += __shfl_xor_sync(FULL, p, off);
                if (lane==0){
                    float val = p + ba1r[jj];
                    unsigned a = wasA + (unsigned)(rank*64 + w*4 + jj)*4u;
                    #pragma unroll
                    for (int r=0;r<CS_;r++) sts_remote(a, (unsigned)r, val);
                }
            }
        }
        __syncthreads();
        if (tid < CS_) bar_arrive_rank(barA, (unsigned)tid);
        bar_wait(barA, ph);

        // ---- phase 5: scores from smem UaH; IC direct from L2 (4-row prefetch) ----
        __half2 was_h2[4];
        #pragma unroll
        for (int j=0;j<4;j++)
            was_h2[j] = __floats2half2_rn(s_was[lane*8+2*j], s_was[lane*8+2*j+1]);

        float l = 0.f, c[8];
        #pragma unroll
        for (int k=0;k<8;k++) c[k]=0.f;

        uint4 icr[4];
        #pragma unroll
        for (int j=0;j<4;j++) icr[j] = __ldcg(&i4[(size_t)j*32]);

        #pragma unroll
        for (int i=0;i<RPW_;i++){
            uint4 cur = icr[i&3];
            if (i+4 < RPW_) icr[i&3] = __ldcg(&i4[(size_t)(i+4)*32]);
            const int row = w*RPW_ + i;
            uint4 u = *(const uint4*)(s_uahB + (size_t)row*512 + lane*16);
            const __half2* h = reinterpret_cast<const __half2*>(&u);
            __half2 acc = __floats2half2_rn(0.f, 0.f);
            #pragma unroll
            for (int q=0;q<4;q++)
                acc = __hfma2(tanh2_a(__hadd2(h[q], was_h2[q])), va_h2[q], acc);
            float2 af = __half22float2(acc);
            float p = af.x + af.y;
            #pragma unroll
            for (int off=16; off; off>>=1) p += __shfl_xor_sync(FULL, p, off);
            float pe = __expf(p + s_ba3[row]);
            l += pe;
            float g[8]; bf8(cur, g);
            #pragma unroll
            for (int k=0;k<8;k++) c[k] = fmaf(pe, g[k], c[k]);
        }

        // ---- phase 6: combine 16 warps; push CTA partial to all ranks ----
        if (lane==0) s_wl[w]=l;
        #pragma unroll
        for (int k=0;k<8;k++) s_wc[w][WCI(lane*8+k)] = c[k];
        __syncthreads();
        if (tid < ON_){
            float sc=0.f;
            #pragma unroll
            for (int r=0;r<NW_;r++) sc += s_wc[r][WCI(tid)];
            unsigned a = cinA + (unsigned)(rank*(ON_+1) + tid)*4u;
            #pragma unroll
            for (int r=0;r<CS_;r++) sts_remote(a, (unsigned)r, sc);
        }
        if (tid == 0){
            float sl=0.f;
            #pragma unroll
            for (int r=0;r<NW_;r++) sl += s_wl[r];
            unsigned a = cinA + (unsigned)(rank*(ON_+1) + ON_)*4u;
            #pragma unroll
            for (int r=0;r<CS_;r++) sts_remote(a, (unsigned)r, sl);
        }
        __syncthreads();
        if (tid < CS_) bar_arrive_rank(barB, (unsigned)tid);
        bar_wait(barB, ph);

        // ---- phase 8: local combine + pred update ----
        if (tid < ON_){
            float csum = s_cin[0][tid] + s_cin[1][tid] + s_cin[2][tid] + s_cin[3][tid];
            float L    = s_cin[0][ON_] + s_cin[1][ON_] + s_cin[2][ON_] + s_cin[3][ON_];
            float pred = woy + uoh + csum / L + s_b34[tid];
            if (rank==0) outB[(size_t)t*ON_ + tid] = pred;
            s_pred[tid] = pred;
        }
    }
}

extern "C" void kernel_launch(void* const* d_in, const int* in_sizes, int n_in,
                              void* d_out, int out_size) {
    const float* inputs = (const float*)d_in[0];
    const float* Wa  = (const float*)d_in[1];
    const float* Ua  = (const float*)d_in[2];
    const float* Va  = (const float*)d_in[3];
    const float* Ba1 = (const float*)d_in[4];
    const float* Ba2 = (const float*)d_in[5];
    const float* Ba3 = (const float*)d_in[6];
    const float* Wo  = (const float*)d_in[7];
    const float* Uo  = (const float*)d_in[8];
    const float* Co  = (const float*)d_in[9];
    const float* Bo2 = (const float*)d_in[10];
    const float* Bo3 = (const float*)d_in[11];
    const float* Bo4 = (const float*)d_in[12];
    const float* emb = (const float*)d_in[13];
    float* out = (float*)d_out;

    static bool attr_done = false;
    if (!attr_done){
        cudaFuncSetAttribute(recur_kernel,
            cudaFuncAttributeMaxDynamicSharedMemorySize, UAH_BYTES);
        attr_done = true;
    }

    w2_kernel<<<32, 256>>>(emb, Wo);
    gemm_pre<<<dim3((BN_*TN_)/128, 6), 256>>>(inputs, Ua, Co, Uo, Ba2, Bo2);
    recur_kernel<<<dim3(CS_, BN_, 1), NT_, UAH_BYTES>>>(Wa, Va, Ba1, Ba3, Bo3, Bo4, out);
}

// round 15
// speedup vs baseline: 1.6572x; 1.6572x over previous
#include <cuda_runtime.h>
#include <cuda_bf16.h>
#include <cuda_fp16.h>
#include <cooperative_groups.h>

namespace cg = cooperative_groups;

#define BN_ 32
#define TN_ 1024
#define DN_ 1024
#define ON_ 256
#define CS_ 4
#define SC_ (TN_/CS_)   /* 256 s-rows per CTA */

// ---- device scratch (static: no runtime allocation) ----
__device__ __align__(128) __half         g_UaH[(size_t)BN_*TN_*ON_]; // inputs@Ua + Ba2  (fp16)
__device__ __align__(128) __nv_bfloat16  g_IC [(size_t)BN_*TN_*ON_]; // inputs@Co        (bf16)
__device__ __align__(128) float          g_UoH[(size_t)BN_*TN_*ON_]; // inputs@Uo + Bo2  (fp32)
__device__ float g_w2[ON_];                                           // emb @ Wo

__device__ __forceinline__ float tanh_a(float x){
    float y; asm("tanh.approx.f32 %0, %1;" : "=f"(y) : "f"(x)); return y;
}
__device__ __forceinline__ __half2 tanh2_a(__half2 x){
    unsigned xi = *reinterpret_cast<unsigned*>(&x), r;
    asm("tanh.approx.f16x2 %0, %1;" : "=r"(r) : "r"(xi));
    return *reinterpret_cast<__half2*>(&r);
}
__device__ __forceinline__ void bf8(const uint4 u, float f[8]){
    f[0]=__int_as_float(u.x<<16); f[1]=__int_as_float(u.x&0xffff0000u);
    f[2]=__int_as_float(u.y<<16); f[3]=__int_as_float(u.y&0xffff0000u);
    f[4]=__int_as_float(u.z<<16); f[5]=__int_as_float(u.z&0xffff0000u);
    f[6]=__int_as_float(u.w<<16); f[7]=__int_as_float(u.w&0xffff0000u);
}

// ---- cluster mbarrier barrier ----
__device__ __forceinline__ void bar_arrive_rank(unsigned addr, unsigned rank){
    asm volatile("{\n\t.reg .b32 ra;\n\t"
                 "mapa.shared::cluster.u32 ra, %0, %1;\n\t"
                 "mbarrier.arrive.release.cluster.shared::cluster.b64 _, [ra];\n\t}"
                 :: "r"(addr), "r"(rank) : "memory");
}
__device__ __forceinline__ void bar_wait(unsigned addr, unsigned parity){
    unsigned done;
    do {
        asm volatile("{\n\t.reg .pred p;\n\t"
            "mbarrier.try_wait.parity.acquire.cluster.shared::cta.b64 p, [%1], %2, 0x989680;\n\t"
            "selp.b32 %0, 1, 0, p;\n\t}"
            : "=r"(done) : "r"(addr), "r"(parity) : "memory");
    } while (!done);
}

// ---- cp.async helpers ----
__device__ __forceinline__ void cp16(unsigned dst, const void* src){
    asm volatile("cp.async.cg.shared.global [%0], [%1], 16;" :: "r"(dst), "l"(src));
}
__device__ __forceinline__ void cp_commit(){
    asm volatile("cp.async.commit_group;" ::: "memory");
}
template<int N> __device__ __forceinline__ void cp_wait(){
    asm volatile("cp.async.wait_group %0;" :: "n"(N) : "memory");
}

// ---- tf32 helpers ----
__device__ __forceinline__ unsigned tf32r(float x){
    unsigned y; asm("cvt.rna.tf32.f32 %0, %1;" : "=r"(y) : "f"(x)); return y;
}
__device__ __forceinline__ void mma_tf32(float d[4],
    unsigned a0, unsigned a1, unsigned a2, unsigned a3,
    unsigned b0, unsigned b1)
{
    asm volatile("mma.sync.aligned.m16n8k8.row.col.f32.tf32.tf32.f32 "
        "{%0,%1,%2,%3}, {%4,%5,%6,%7}, {%8,%9}, {%0,%1,%2,%3};"
        : "+f"(d[0]), "+f"(d[1]), "+f"(d[2]), "+f"(d[3])
        : "r"(a0), "r"(a1), "r"(a2), "r"(a3), "r"(b0), "r"(b1));
}

// ================= w2 = emb @ Wo =================
__global__ void __launch_bounds__(256) w2_kernel(const float* __restrict__ emb,
                                                 const float* __restrict__ Wo){
    int w = threadIdx.x >> 5, lane = threadIdx.x & 31;
    int i = blockIdx.x * 8 + w;
    float a = 0.f;
    #pragma unroll
    for (int j = lane; j < ON_; j += 32) a = fmaf(emb[i*ON_+j], Wo[j], a);
    #pragma unroll
    for (int off=16; off; off>>=1) a += __shfl_xor_sync(0xffffffffu, a, off);
    if (lane==0) g_w2[i] = a;
}

// ======= tf32 tensor-core GEMM for UaH (fp16,+Ba2) and IC (bf16) =======
// grid (256 mtiles, 2 ncols, 2 which{0=Ua,1=Co}), 256 threads (8 warps: 4M x 2N)
#define ASTR 36
#define WSTR 136
__global__ void __launch_bounds__(256,2) gemm_mma(
    const float* __restrict__ A,  const float* __restrict__ Ua,
    const float* __restrict__ Co, const float* __restrict__ Ba2)
{
    __shared__ float As[128*ASTR];   // [m][k] k-chunk=32, row stride 36
    __shared__ float Ws[32*WSTR];    // [k][n] n-tile=128, row stride 136

    const int tid  = threadIdx.x;
    const int m0   = blockIdx.x * 128;
    const int nc0  = blockIdx.y * 128;
    const int which= blockIdx.z;
    const float* W = which ? Co : Ua;

    const int ww = tid >> 5, lane = tid & 31;
    const int wm = ww & 3, wn = ww >> 2;       // warp tile: rows wm*32, cols wn*64
    const int g  = lane >> 2, tc = lane & 3;

    float acc[2][8][4];
    #pragma unroll
    for (int mt=0;mt<2;mt++)
        #pragma unroll
        for (int nt=0;nt<8;nt++)
            #pragma unroll
            for (int q=0;q<4;q++) acc[mt][nt][q]=0.f;

    const int arow = tid >> 1, akq = tid & 1;          // A: 2 threads/row, 16 k each
    const int wrow = tid >> 3, wseg = tid & 7;         // W: 8 threads/row, 16 n each

    for (int kc=0; kc<32; kc++){
        const int k0 = kc*32;
        __syncthreads();
        #pragma unroll
        for (int q=0;q<4;q++){
            float4 v = *(const float4*)&A[(size_t)(m0+arow)*DN_ + k0 + akq*16 + q*4];
            float* d = &As[arow*ASTR + akq*16 + q*4];
            d[0]=__uint_as_float(tf32r(v.x)); d[1]=__uint_as_float(tf32r(v.y));
            d[2]=__uint_as_float(tf32r(v.z)); d[3]=__uint_as_float(tf32r(v.w));
        }
        #pragma unroll
        for (int q=0;q<4;q++){
            float4 v = *(const float4*)&W[(size_t)(k0+wrow)*ON_ + nc0 + wseg*16 + q*4];
            float* d = &Ws[wrow*WSTR + wseg*16 + q*4];
            d[0]=__uint_as_float(tf32r(v.x)); d[1]=__uint_as_float(tf32r(v.y));
            d[2]=__uint_as_float(tf32r(v.z)); d[3]=__uint_as_float(tf32r(v.w));
        }
        __syncthreads();

        const unsigned* Au = (const unsigned*)As;
        const unsigned* Wu = (const unsigned*)Ws;
        #pragma unroll
        for (int ks=0; ks<4; ks++){
            const int kb = ks*8;
            unsigned a[2][4];
            #pragma unroll
            for (int mt=0;mt<2;mt++){
                const int rm = wm*32 + mt*16;
                a[mt][0] = Au[(rm+g  )*ASTR + kb + tc];
                a[mt][1] = Au[(rm+g+8)*ASTR + kb + tc];
                a[mt][2] = Au[(rm+g  )*ASTR + kb + tc + 4];
                a[mt][3] = Au[(rm+g+8)*ASTR + kb + tc + 4];
            }
            #pragma unroll
            for (int nt=0;nt<8;nt++){
                const int cn = wn*64 + nt*8;
                unsigned b0 = Wu[(kb+tc  )*WSTR + cn + g];
                unsigned b1 = Wu[(kb+tc+4)*WSTR + cn + g];
                mma_tf32(acc[0][nt], a[0][0],a[0][1],a[0][2],a[0][3], b0,b1);
                mma_tf32(acc[1][nt], a[1][0],a[1][1],a[1][2],a[1][3], b0,b1);
            }
        }
    }

    // epilogue: c0/c1 at (row g, cols tc*2, tc*2+1); c2/c3 at row g+8
    #pragma unroll
    for (int mt=0;mt<2;mt++){
        #pragma unroll
        for (int nt=0;nt<8;nt++){
            const int r0 = m0 + wm*32 + mt*16 + g;
            const int c0 = nc0 + wn*64 + nt*8 + tc*2;
            #pragma unroll
            for (int half=0; half<2; half++){
                const int r = r0 + half*8;
                const float v0 = acc[mt][nt][half*2+0];
                const float v1 = acc[mt][nt][half*2+1];
                const size_t oi = (size_t)r*ON_ + c0;
                if (which==0){
                    const int trow = r & (TN_-1);
                    __half2 h = __floats2half2_rn(v0 + Ba2[trow*ON_ + c0],
                                                  v1 + Ba2[trow*ON_ + c0 + 1]);
                    *(__half2*)&g_UaH[oi] = h;
                } else {
                    __nv_bfloat162 h;
                    h.x = __float2bfloat16(v0);
                    h.y = __float2bfloat16(v1);
                    *(__nv_bfloat162*)&g_IC[oi] = h;
                }
            }
        }
    }
}

// ======= fp32 SIMT GEMM for UoH only: [32768,1024] @ [1024,256] =======
__global__ void __launch_bounds__(256,2) gemm_uo(
    const float* __restrict__ A, const float* __restrict__ Uo,
    const float* __restrict__ Bo2)
{
    __shared__ float As[16][128];
    __shared__ float Bs[16][128];
    const int tid = threadIdx.x;
    const int mt = blockIdx.x, nt = blockIdx.y;
    const int ncol0 = nt * 128;
    const int m0 = mt * 128;
    const int tx = tid & 15, ty = tid >> 4;

    float acc[8][8];
    #pragma unroll
    for (int i=0;i<8;i++)
        #pragma unroll
        for (int j=0;j<8;j++) acc[i][j]=0.f;

    for (int k0=0;k0<DN_;k0+=16){
        #pragma unroll
        for (int q=0;q<2;q++){
            int f4 = tid + q*256;
            int row = f4 >> 2, c4 = f4 & 3;
            float4 v = *(const float4*)&A[(size_t)(m0+row)*DN_ + k0 + c4*4];
            As[c4*4+0][row]=v.x; As[c4*4+1][row]=v.y;
            As[c4*4+2][row]=v.z; As[c4*4+3][row]=v.w;
        }
        #pragma unroll
        for (int q=0;q<2;q++){
            int f4 = tid + q*256;
            int kk = f4 >> 5, c4 = f4 & 31;
            *(float4*)&Bs[kk][c4*4] = *(const float4*)&Uo[(size_t)(k0+kk)*ON_ + ncol0 + c4*4];
        }
        __syncthreads();
        #pragma unroll
        for (int kk=0;kk<16;kk++){
            float a[8], bb[8];
            *(float4*)&a[0]  = *(const float4*)&As[kk][ty*8];
            *(float4*)&a[4]  = *(const float4*)&As[kk][ty*8+4];
            *(float4*)&bb[0] = *(const float4*)&Bs[kk][tx*8];
            *(float4*)&bb[4] = *(const float4*)&Bs[kk][tx*8+4];
            #pragma unroll
            for (int i=0;i<8;i++)
                #pragma unroll
                for (int j=0;j<8;j++) acc[i][j] = fmaf(a[i], bb[j], acc[i][j]);
        }
        __syncthreads();
    }
    #pragma unroll
    for (int i=0;i<8;i++){
        int mrow = m0 + ty*8 + i;
        #pragma unroll
        for (int j=0;j<8;j++){
            int c = ncol0 + tx*8 + j;
            g_UoH[(size_t)mrow*ON_ + c] = acc[i][j] + Bo2[c];
        }
    }
}

#define WCI(j) ((((j)>>5)*33) + ((j)&31))
#define UAH_BYTES (SC_*ON_*2)          /* 131072 */
#define ICR_BYTES (8*2*8*512)          /* 8 warps x 2 stages x 8 rows x 512B */
#define DSMEM_BYTES (UAH_BYTES + ICR_BYTES)

// ============ persistent per-batch cluster recurrence (R11, verbatim) ============
__global__ void __cluster_dims__(CS_,1,1) __launch_bounds__(256,1)
recur_kernel(const float* __restrict__ Wa,  const float* __restrict__ Va,
             const float* __restrict__ Ba1, const float* __restrict__ Ba3,
             const float* __restrict__ Bo3, const float* __restrict__ Bo4,
             float* __restrict__ out)
{
    extern __shared__ __align__(128) char dsm[];
    char* s_uahB = dsm;                       // [256][256] fp16, row = 512B
    char* s_icrB = dsm + UAH_BYTES;           // warp w: +w*8192; stage s: +s*4096; row r: +r*512

    __shared__ float s_pred[ON_];
    __shared__ float s_q[ON_];
    __shared__ float s_was[ON_];
    __shared__ float s_wasq[64];
    __shared__ float s_ba3[SC_];
    __shared__ float s_b34[ON_];
    __shared__ float s_w2[ON_];
    __shared__ float s_wc[8][8*33];
    __shared__ float s_wl[8];
    __shared__ float s_cexp[ON_+1];
    __shared__ float s_redA[8], s_redB[8];
    __shared__ __align__(16) unsigned long long s_bars[2];

    cg::cluster_group cluster = cg::this_cluster();
    const int rank = blockIdx.x;
    const int b    = blockIdx.y;
    const int tid  = threadIdx.x;
    const int w = tid >> 5, lane = tid & 31;
    const unsigned FULL = 0xffffffffu;

    s_pred[tid] = 0.f;
    s_ba3[tid]  = Ba3[rank*SC_ + tid];
    s_b34[tid]  = Bo3[tid] + Bo4[tid];
    s_w2[tid]   = g_w2[tid];

    float Wr[8][8];
    #pragma unroll
    for (int jj=0;jj<8;jj++)
        #pragma unroll
        for (int k=0;k<8;k++)
            Wr[jj][k] = Wa[(size_t)(lane + 32*k)*ON_ + rank*64 + w*8 + jj];
    float ba1r[8];
    #pragma unroll
    for (int jj=0;jj<8;jj++) ba1r[jj] = Ba1[rank*64 + w*8 + jj];

    __half2 va_h2[4];
    #pragma unroll
    for (int j=0;j<4;j++)
        va_h2[j] = __floats2half2_rn(Va[lane*8+2*j], Va[lane*8+2*j+1]);

    unsigned barA = (unsigned)__cvta_generic_to_shared(&s_bars[0]);
    unsigned barB = (unsigned)__cvta_generic_to_shared(&s_bars[1]);
    if (tid == 0){
        asm volatile("mbarrier.init.shared.b64 [%0], %1;" :: "r"(barA), "r"(CS_) : "memory");
        asm volatile("mbarrier.init.shared.b64 [%0], %1;" :: "r"(barB), "r"(CS_) : "memory");
    }

    const __half*        uahB = g_UaH + (size_t)b*TN_*ON_ + (size_t)rank*SC_*ON_;
    const __nv_bfloat16* icB  = g_IC  + (size_t)b*TN_*ON_ + (size_t)rank*SC_*ON_;
    const float* uohB = g_UoH + (size_t)b*TN_*ON_;
    float* outB = out + (size_t)b*TN_*ON_;

    {
        const uint4* src = (const uint4*)uahB;
        uint4* dst = (uint4*)s_uahB;
        #pragma unroll
        for (int i=0;i<32;i++) dst[tid + i*256] = src[tid + i*256];
    }

    unsigned icr = (unsigned)__cvta_generic_to_shared(s_icrB) + w*8192 + lane*16;
    const char* icw = (const char*)icB + (size_t)w*32*512 + lane*16;
    char* icr_gen = s_icrB + w*8192 + lane*16;

    #pragma unroll
    for (int r=0;r<8;r++) cp16(icr + r*512, icw + r*512);
    cp_commit();

    const float* peer_wasq[CS_];
    const float* peer_cexp[CS_];
    #pragma unroll
    for (int r=0;r<CS_;r++){
        peer_wasq[r] = (const float*)cluster.map_shared_rank((void*)s_wasq, r);
        peer_cexp[r] = (const float*)cluster.map_shared_rank((void*)s_cexp, r);
    }
    cluster.sync();

    for (int t=0; t<TN_; t++){
        const unsigned ph = (unsigned)(t & 1);

        float uoh = __ldcg(&uohB[(size_t)((t + TN_ - 1) & (TN_-1))*ON_ + tid]);

        float pv = s_pred[tid];
        s_q[tid] = tanh_a(pv);
        float e  = __expf(pv);
        float en = e, ew = e * s_w2[tid];
        #pragma unroll
        for (int off=16; off; off>>=1){
            en += __shfl_xor_sync(FULL, en, off);
            ew += __shfl_xor_sync(FULL, ew, off);
        }
        if (lane==0){ s_redA[w]=en; s_redB[w]=ew; }
        __syncthreads();
        float sn=0.f, sw=0.f;
        #pragma unroll
        for (int r=0;r<8;r++){ sn+=s_redA[r]; sw+=s_redB[r]; }
        float woy = sw / sn;

        float qr[8];
        #pragma unroll
        for (int k=0;k<8;k++) qr[k] = s_q[lane + 32*k];
        #pragma unroll
        for (int jj=0;jj<8;jj++){
            float p = 0.f;
            #pragma unroll
            for (int k=0;k<8;k++) p = fmaf(qr[k], Wr[jj][k], p);
            #pragma unroll
            for (int off=16; off; off>>=1) p += __shfl_xor_sync(FULL, p, off);
            if (lane==0) s_wasq[w*8+jj] = p + ba1r[jj];
        }
        __syncthreads();
        if (tid < CS_) bar_arrive_rank(barA, (unsigned)tid);
        bar_wait(barA, ph);

        s_was[tid] = peer_wasq[tid>>6][tid & 63];
        __syncthreads();
        __half2 was_h2[4];
        #pragma unroll
        for (int j=0;j<4;j++)
            was_h2[j] = __floats2half2_rn(s_was[lane*8+2*j], s_was[lane*8+2*j+1]);

        float l = 0.f, c[8];
        #pragma unroll
        for (int k=0;k<8;k++) c[k]=0.f;

        #pragma unroll
        for (int chunk=0; chunk<4; chunk++){
            if (chunk < 3){
                #pragma unroll
                for (int r=0;r<8;r++)
                    cp16(icr + ((chunk+1)&1)*4096 + r*512, icw + (size_t)((chunk+1)*8+r)*512);
                cp_commit();
                cp_wait<1>();
            } else if (t < TN_-1){
                #pragma unroll
                for (int r=0;r<8;r++)
                    cp16(icr + r*512, icw + r*512);
                cp_commit();
                cp_wait<1>();
            } else {
                cp_wait<0>();
            }
            const char* ring = icr_gen + (chunk&1)*4096;
            #pragma unroll
            for (int r=0;r<8;r++){
                const int row = w*32 + chunk*8 + r;
                uint4 u = *(const uint4*)(s_uahB + (size_t)row*512 + lane*16);
                const __half2* h = reinterpret_cast<const __half2*>(&u);
                __half2 acc = __floats2half2_rn(0.f, 0.f);
                #pragma unroll
                for (int q=0;q<4;q++)
                    acc = __hfma2(tanh2_a(__hadd2(h[q], was_h2[q])), va_h2[q], acc);
                float2 af = __half22float2(acc);
                float p = af.x + af.y;
                #pragma unroll
                for (int off=16; off; off>>=1) p += __shfl_xor_sync(FULL, p, off);
                float pe = __expf(p + s_ba3[row]);
                l += pe;
                uint4 v = *(const uint4*)(ring + r*512);
                float g[8]; bf8(v, g);
                #pragma unroll
                for (int k=0;k<8;k++) c[k] = fmaf(pe, g[k], c[k]);
            }
        }

        if (lane==0) s_wl[w]=l;
        #pragma unroll
        for (int k=0;k<8;k++) s_wc[w][WCI(lane*8+k)] = c[k];
        __syncthreads();
        {
            float sc=0.f;
            #pragma unroll
            for (int r=0;r<8;r++) sc += s_wc[r][WCI(tid)];
            s_cexp[tid] = sc;
            if (tid==0){
                float sl=0.f;
                #pragma unroll
                for (int r=0;r<8;r++) sl += s_wl[r];
                s_cexp[ON_] = sl;
            }
        }
        __syncthreads();
        if (tid < CS_) bar_arrive_rank(barB, (unsigned)tid);
        bar_wait(barB, ph);

        float csum=0.f, L=0.f;
        #pragma unroll
        for (int r=0;r<CS_;r++){
            csum += peer_cexp[r][tid];
            L    += peer_cexp[r][ON_];
        }
        float coc = csum / L;
        float pred = woy + uoh + coc + s_b34[tid];
        if (rank==0) outB[(size_t)t*ON_ + tid] = pred;
        s_pred[tid] = pred;
    }
}

extern "C" void kernel_launch(void* const* d_in, const int* in_sizes, int n_in,
                              void* d_out, int out_size) {
    const float* inputs = (const float*)d_in[0];
    const float* Wa  = (const float*)d_in[1];
    const float* Ua  = (const float*)d_in[2];
    const float* Va  = (const float*)d_in[3];
    const float* Ba1 = (const float*)d_in[4];
    const float* Ba2 = (const float*)d_in[5];
    const float* Ba3 = (const float*)d_in[6];
    const float* Wo  = (const float*)d_in[7];
    const float* Uo  = (const float*)d_in[8];
    const float* Co  = (const float*)d_in[9];
    const float* Bo2 = (const float*)d_in[10];
    const float* Bo3 = (const float*)d_in[11];
    const float* Bo4 = (const float*)d_in[12];
    const float* emb = (const float*)d_in[13];
    float* out = (float*)d_out;

    static bool attr_done = false;
    if (!attr_done){
        cudaFuncSetAttribute(recur_kernel,
            cudaFuncAttributeMaxDynamicSharedMemorySize, DSMEM_BYTES);
        attr_done = true;
    }

    w2_kernel<<<32, 256>>>(emb, Wo);
    gemm_mma<<<dim3((BN_*TN_)/128, 2, 2), 256>>>(inputs, Ua, Co, Ba2);
    gemm_uo<<<dim3((BN_*TN_)/128, 2), 256>>>(inputs, Uo, Bo2);
    recur_kernel<<<dim3(CS_, BN_, 1), 256, DSMEM_BYTES>>>(Wa, Va, Ba1, Ba3, Bo3, Bo4, out);
}